// round 4
// baseline (speedup 1.0000x reference)
#include <cuda_runtime.h>
#include <math_constants.h>

// EvenLayer min-sum check-node update — exact-fit grid, no bounds predicate.
//
// Structure (proved in R0, rel_err = 0.0): the lexsort permutation in the
// reference mask builder is the identity, so check(e) = e % 600 and the
// neighbor set of edge e is { (e%600) + 600*m : m=0..5 } \ {e}.
//
// Shape: grid (5, 8) x 120 threads = exactly 600 checks x 8 batches.
// No tail predicate before the loads; 12 front-batched LDGs (one exposed
// DRAM round trip); all strided offsets are compile-time immediates.

#define N_CHK 600
#define BATCH 8
#define E     3600
#define DEG   6

__global__ __launch_bounds__(120)
void even_layer_kernel(const float* __restrict__ x,
                       const float* __restrict__ bias,
                       float* __restrict__ out)
{
    const int c = blockIdx.x * 120 + threadIdx.x;   // check id, exact 0..599
    const int b = blockIdx.y;                        // batch id

    const int base = b * E + c;
    const float* __restrict__ xb = x + base;
    const float* __restrict__ bb = bias + c;
    float* __restrict__ ob       = out + base;

    // Front-batch ALL independent loads: 12 LDGs in flight.
    float v[DEG], bs[DEG];
#pragma unroll
    for (int m = 0; m < DEG; ++m) v[m]  = xb[m * N_CHK];
#pragma unroll
    for (int m = 0; m < DEG; ++m) bs[m] = bb[m * N_CHK];

#pragma unroll
    for (int i = 0; i < DEG; ++i) {        // exclusive reduce per edge
        float p  = 1.0f;
        float mn = CUDART_INF_F;
#pragma unroll
        for (int k = 0; k < DEG; ++k) {
            if (k != i) {
                p  = p * v[k];
                mn = fminf(mn, fabsf(v[k]));
            }
        }
        // sign() incl. sign(0)=0, matching jnp.sign(prod(...)); keep the
        // actual fp32 product (bit-XOR sign would diverge on underflow).
        const float s = (p > 0.0f) ? 1.0f : ((p < 0.0f) ? -1.0f : 0.0f);
        ob[i * N_CHK] = s * fmaxf(mn - bs[i], 0.0f);
    }
}

extern "C" void kernel_launch(void* const* d_in, const int* in_sizes, int n_in,
                              void* d_out, int out_size)
{
    // metadata order: inputs [BATCH,E] f32, bias [1,E] f32, inf_mask [E,E] f32 (unused)
    const float* x    = (const float*)d_in[0];
    const float* bias = (const float*)d_in[1];
    float* out        = (float*)d_out;

    dim3 grid(5, BATCH);                 // 5 * 120 = 600 checks, 8 batches
    even_layer_kernel<<<grid, 120>>>(x, bias, out);
}